// round 6
// baseline (speedup 1.0000x reference)
#include <cuda_runtime.h>
#include <cuda_bf16.h>
#include <cuda_fp16.h>
#include <cstdint>

#define N_NODES 100000
#define DEG     16
#define E_EDGES (N_NODES * DEG)
#define ALPHA   0.2f

// Scratch (static __device__ — no allocs allowed)
__device__ __half  g_h16   [(size_t)N_NODES * 128];  // [h_high(64) | h_low(64)] fp16
__device__ __half  g_hagg16[(size_t)N_NODES * 128];  // [hagg_high | hagg_low]  fp16
__device__ float2  g_ssrc[N_NODES];                  // (ssrc_h, ssrc_l)  fp32
__device__ float2  g_sdst[N_NODES];                  // (sdst_h, sdst_l)  fp32
// W as B-operand [n=128][k=128] bf16 hi/lo, chunk-swizzled (ldmatrix-ready)
__device__ uint32_t g_Wblk_hi[8192];
__device__ uint32_t g_Wblk_lo[8192];

__device__ __forceinline__ uint32_t sw_off(int row, int k) {
    return (uint32_t)(row * 256 + ((((k >> 3) ^ (row & 7)) << 4) | ((k & 7) << 1)));
}

__device__ __forceinline__ uint32_t smem_u32(const void* p) {
    uint32_t a;
    asm("{ .reg .u64 t; cvta.to.shared.u64 t, %1; cvt.u32.u64 %0, t; }" : "=r"(a) : "l"(p));
    return a;
}

__device__ __forceinline__ void ldmatrix_x4(uint32_t* r, uint32_t addr) {
    asm volatile("ldmatrix.sync.aligned.m8n8.x4.shared.b16 {%0,%1,%2,%3}, [%4];"
                 : "=r"(r[0]), "=r"(r[1]), "=r"(r[2]), "=r"(r[3]) : "r"(addr));
}

__device__ __forceinline__ void mma_bf16(float* c, const uint32_t* a, uint32_t b0, uint32_t b1) {
    asm volatile(
        "mma.sync.aligned.m16n8k16.row.col.f32.bf16.bf16.f32 "
        "{%0,%1,%2,%3}, {%4,%5,%6,%7}, {%8,%9}, {%0,%1,%2,%3};"
        : "+f"(c[0]), "+f"(c[1]), "+f"(c[2]), "+f"(c[3])
        : "r"(a[0]), "r"(a[1]), "r"(a[2]), "r"(a[3]), "r"(b0), "r"(b1));
}

// ---------------------------------------------------------------------------
// K0: bake Wcat as B-operand [n][k] bf16 hi/lo, swizzled. B[n][k] = Wcat[k][n].
// ---------------------------------------------------------------------------
__global__ void k_wprep(const float* __restrict__ Wh, const float* __restrict__ Wl)
{
    int idx = blockIdx.x * blockDim.x + threadIdx.x;
    if (idx >= 128 * 64) return;
    int n = idx >> 6, kp = idx & 63, k = kp * 2;
    const float* Ws = (n < 64) ? Wh : Wl;
    int c = n & 63;
    float w0 = Ws[k * 64 + c];
    float w1 = Ws[(k + 1) * 64 + c];

    __nv_bfloat16 h0 = __float2bfloat16_rn(w0);
    __nv_bfloat16 h1 = __float2bfloat16_rn(w1);
    __nv_bfloat16 l0 = __float2bfloat16_rn(w0 - __bfloat162float(h0));
    __nv_bfloat16 l1 = __float2bfloat16_rn(w1 - __bfloat162float(h1));

    uint32_t hp = ((uint32_t)__bfloat16_as_ushort(h1) << 16) | __bfloat16_as_ushort(h0);
    uint32_t lp = ((uint32_t)__bfloat16_as_ushort(l1) << 16) | __bfloat16_as_ushort(l0);

    uint32_t off = sw_off(n, k);
    *(uint32_t*)((char*)g_Wblk_hi + off) = hp;
    *(uint32_t*)((char*)g_Wblk_lo + off) = lp;
}

// ---------------------------------------------------------------------------
// K1: mma.sync bf16 split GEMM + fused epilogue (h fp16, attention scalars fp32)
// ---------------------------------------------------------------------------
#define SM_AHI 0
#define SM_ALO 32768
#define SM_WHI 65536
#define SM_WLO 98304
#define SM_TOTAL 131072

__global__ __launch_bounds__(256, 1)
void k_gemm_mma(const float* __restrict__ A,
                const float* __restrict__ ah,
                const float* __restrict__ al)
{
    extern __shared__ char smem[];
    const uint32_t sbase = smem_u32(smem);
    const int tid = threadIdx.x;
    const int wid = tid >> 5;
    const int lane = tid & 31;
    const int rowBase = blockIdx.x * 128;

    {
        const uint4* shi = (const uint4*)g_Wblk_hi;
        const uint4* slo = (const uint4*)g_Wblk_lo;
        uint4* dhi = (uint4*)(smem + SM_WHI);
        uint4* dlo = (uint4*)(smem + SM_WLO);
#pragma unroll
        for (int i = tid; i < 2048; i += 256) { dhi[i] = shi[i]; dlo[i] = slo[i]; }
    }

    for (int i = tid; i < 8192; i += 256) {
        int r = i >> 6, kp = i & 63, k = kp * 2;
        int node = rowBase + r;
        float2 v = make_float2(0.f, 0.f);
        if (node < N_NODES) v = *(const float2*)(A + (size_t)node * 128 + k);

        __nv_bfloat16 h0 = __float2bfloat16_rn(v.x);
        __nv_bfloat16 h1 = __float2bfloat16_rn(v.y);
        __nv_bfloat16 l0 = __float2bfloat16_rn(v.x - __bfloat162float(h0));
        __nv_bfloat16 l1 = __float2bfloat16_rn(v.y - __bfloat162float(h1));
        uint32_t hp = ((uint32_t)__bfloat16_as_ushort(h1) << 16) | __bfloat16_as_ushort(h0);
        uint32_t lp = ((uint32_t)__bfloat16_as_ushort(l1) << 16) | __bfloat16_as_ushort(l0);

        uint32_t off = sw_off(r, k);
        *(uint32_t*)(smem + SM_AHI + off) = hp;
        *(uint32_t*)(smem + SM_ALO + off) = lp;
    }
    __syncthreads();

    const int m_base = wid * 16;
    float c[16][4];
#pragma unroll
    for (int j = 0; j < 16; j++)
#pragma unroll
        for (int q = 0; q < 4; q++) c[j][q] = 0.f;

    const int g  = lane >> 3;
    const int rr = lane & 7;
    const int a_row = m_base + ((g & 1) << 3) + rr;
    const int a_kof = (g >> 1) << 3;
    const int b_nof = ((g >> 1) << 3) + rr;
    const int b_kof = (g & 1) << 3;

#pragma unroll
    for (int pass = 0; pass < 3; pass++) {
        const uint32_t aBase = sbase + ((pass == 2) ? SM_ALO : SM_AHI);
        const uint32_t bBase = sbase + ((pass == 1) ? SM_WLO : SM_WHI);
#pragma unroll
        for (int ks = 0; ks < 8; ks++) {
            const int kb = ks * 16;
            uint32_t a[4];
            ldmatrix_x4(a, aBase + sw_off(a_row, kb + a_kof));
#pragma unroll
            for (int nt = 0; nt < 8; nt++) {
                uint32_t b[4];
                ldmatrix_x4(b, bBase + sw_off(nt * 16 + b_nof, kb + b_kof));
                mma_bf16(c[2 * nt],     a, b[0], b[1]);
                mma_bf16(c[2 * nt + 1], a, b[2], b[3]);
            }
        }
    }

    // --- writeout h as fp16 ---
    const int row0 = rowBase + m_base + (lane >> 2);
    const int cb   = (lane & 3) * 2;
    if (row0 < N_NODES) {
        __half* o = g_h16 + (size_t)row0 * 128;
#pragma unroll
        for (int j = 0; j < 16; j++)
            *(__half2*)(o + j * 8 + cb) = __floats2half2_rn(c[j][0], c[j][1]);
    }
    if (row0 + 8 < N_NODES) {
        __half* o = g_h16 + (size_t)(row0 + 8) * 128;
#pragma unroll
        for (int j = 0; j < 16; j++)
            *(__half2*)(o + j * 8 + cb) = __floats2half2_rn(c[j][2], c[j][3]);
    }

    // --- attention scalars (fp32, from register accumulators) ---
    float ssh0 = 0.f, sdh0 = 0.f, ssl0 = 0.f, sdl0 = 0.f;   // row0
    float ssh1 = 0.f, sdh1 = 0.f, ssl1 = 0.f, sdl1 = 0.f;   // row0+8
#pragma unroll
    for (int j = 0; j < 8; j++) {
        int c0 = j * 8 + cb;
        float2 as = *(const float2*)(ah + c0);
        float2 ad = *(const float2*)(ah + 64 + c0);
        ssh0 += c[j][0] * as.x + c[j][1] * as.y;
        sdh0 += c[j][0] * ad.x + c[j][1] * ad.y;
        ssh1 += c[j][2] * as.x + c[j][3] * as.y;
        sdh1 += c[j][2] * ad.x + c[j][3] * ad.y;
    }
#pragma unroll
    for (int j = 8; j < 16; j++) {
        int c0 = (j - 8) * 8 + cb;
        float2 as = *(const float2*)(al + c0);
        float2 ad = *(const float2*)(al + 64 + c0);
        ssl0 += c[j][0] * as.x + c[j][1] * as.y;
        sdl0 += c[j][0] * ad.x + c[j][1] * ad.y;
        ssl1 += c[j][2] * as.x + c[j][3] * as.y;
        sdl1 += c[j][2] * ad.x + c[j][3] * ad.y;
    }
    const unsigned FULL = 0xffffffffu;
#pragma unroll
    for (int off = 1; off <= 2; off <<= 1) {
        ssh0 += __shfl_xor_sync(FULL, ssh0, off);
        sdh0 += __shfl_xor_sync(FULL, sdh0, off);
        ssl0 += __shfl_xor_sync(FULL, ssl0, off);
        sdl0 += __shfl_xor_sync(FULL, sdl0, off);
        ssh1 += __shfl_xor_sync(FULL, ssh1, off);
        sdh1 += __shfl_xor_sync(FULL, sdh1, off);
        ssl1 += __shfl_xor_sync(FULL, ssl1, off);
        sdl1 += __shfl_xor_sync(FULL, sdl1, off);
    }
    if ((lane & 3) == 0) {
        if (row0 < N_NODES) {
            g_ssrc[row0] = make_float2(ssh0, ssl0);
            g_sdst[row0] = make_float2(sdh0, sdl0);
        }
        if (row0 + 8 < N_NODES) {
            g_ssrc[row0 + 8] = make_float2(ssh1, ssl1);
            g_sdst[row0 + 8] = make_float2(sdh1, sdl1);
        }
    }
}

// ---------------------------------------------------------------------------
// K2: per-node warp aggregation. 2 edges/iter: half-warp covers 256B row (uint4).
// ---------------------------------------------------------------------------
__global__ __launch_bounds__(256)
void k_agg(const int* __restrict__ dst_arr)
{
    const int warp = (blockIdx.x * blockDim.x + threadIdx.x) >> 5;
    const int lane = threadIdx.x & 31;
    if (warp >= N_NODES) return;
    const int i = warp;
    const unsigned FULL = 0xffffffffu;

    int d = 0;
    if (lane < DEG) d = dst_arr[i * DEG + lane];

    const int side = lane >> 4;     // 0: even edges, 1: odd edges
    const int sub  = lane & 15;     // covers fp16 cols [8*sub, 8*sub+8)

    float acc[8];
#pragma unroll
    for (int j = 0; j < 8; j++) acc[j] = 0.f;

#pragma unroll
    for (int t = 0; t < 8; t++) {
        int de = __shfl_sync(FULL, d, 2 * t + side);
        uint4 raw = *(const uint4*)(g_h16 + (size_t)de * 128 + sub * 8);
        const __half2* hp = (const __half2*)&raw;
#pragma unroll
        for (int q = 0; q < 4; q++) {
            float2 f = __half22float2(hp[q]);
            acc[2 * q]     += f.x;
            acc[2 * q + 1] += f.y;
        }
    }
    // combine even/odd halves
#pragma unroll
    for (int j = 0; j < 8; j++)
        acc[j] += __shfl_xor_sync(FULL, acc[j], 16);

    if (lane < 16) {
        uint4 sraw = *(const uint4*)(g_h16 + (size_t)i * 128 + sub * 8);
        const __half2* sp = (const __half2*)&sraw;
        float sgn = (sub < 8) ? 1.f : -1.f;
        uint4 ov;
        __half2* op = (__half2*)&ov;
#pragma unroll
        for (int q = 0; q < 4; q++) {
            float2 s = __half22float2(sp[q]);
            op[q] = __floats2half2_rn(16.f * s.x + sgn * acc[2 * q],
                                      16.f * s.y + sgn * acc[2 * q + 1]);
        }
        *(uint4*)(g_hagg16 + (size_t)i * 128 + sub * 8) = ov;
    }
}

// ---------------------------------------------------------------------------
// K3: weighting + output. 2 edges/iter, uint4 gathers, cross-half combines.
// ---------------------------------------------------------------------------
__global__ __launch_bounds__(256)
void k_out(const int* __restrict__ dst_arr, float* __restrict__ out)
{
    const int warp = (blockIdx.x * blockDim.x + threadIdx.x) >> 5;
    const int lane = threadIdx.x & 31;
    if (warp >= N_NODES) return;
    const int i = warp;
    const unsigned FULL = 0xffffffffu;

    int d = 0;
    if (lane < DEG) d = dst_arr[i * DEG + lane];

    float2 si = g_ssrc[i];   // broadcast

    float eh = 0.f, el = 0.f;
    if (lane < DEG) {
        float2 sd = g_sdst[d];
        float sh = si.x + sd.x;
        float sl = si.y + sd.y;
        float lh = sh > 0.f ? sh : ALPHA * sh;
        float ll = sl > 0.f ? sl : ALPHA * sl;
        eh = __expf(-lh);
        el = __expf(-ll);
    }

    // raw rowsums over the 16 edge lanes (lanes>=16 contribute 0)
    float rh = eh, rl = el;
#pragma unroll
    for (int off = 8; off; off >>= 1) {
        rh += __shfl_xor_sync(FULL, rh, off);
        rl += __shfl_xor_sync(FULL, rl, off);
    }
    rh = __shfl_sync(FULL, rh, 0);
    rl = __shfl_sync(FULL, rl, 0);

    float ehc = fminf(eh, 6.f);
    float elc = fminf(el, 6.f);

    const int side = lane >> 4;     // 0: even edges, 1: odd edges
    const int sub  = lane & 15;     // fp16 cols [8*sub, 8*sub+8)

    float acc[8];
#pragma unroll
    for (int j = 0; j < 8; j++) acc[j] = 0.f;

#pragma unroll
    for (int t = 0; t < 8; t++) {
        int e = 2 * t + side;
        int   de = __shfl_sync(FULL, d,   e);
        float wh = __shfl_sync(FULL, ehc, e);
        float wl = __shfl_sync(FULL, elc, e);
        float w  = (sub < 8) ? wh : wl;
        uint4 raw = *(const uint4*)(g_hagg16 + (size_t)de * 128 + sub * 8);
        const __half2* hp = (const __half2*)&raw;
#pragma unroll
        for (int q = 0; q < 4; q++) {
            float2 f = __half22float2(hp[q]);
            acc[2 * q]     += w * f.x;
            acc[2 * q + 1] += w * f.y;
        }
    }
    // combine even/odd edge halves
#pragma unroll
    for (int j = 0; j < 8; j++)
        acc[j] += __shfl_xor_sync(FULL, acc[j], 16);

    // normalize per half (lanes 0-7: high cols, lanes 8-15: low cols)
    float inv = (sub < 8) ? (1.f / rh) : (1.f / rl);
#pragma unroll
    for (int j = 0; j < 8; j++) acc[j] *= inv;

    // bring low-half (lane 8+j) onto lane j
    float part[8];
#pragma unroll
    for (int j = 0; j < 8; j++)
        part[j] = __shfl_xor_sync(FULL, acc[j], 8);

    if (lane < 8) {
        float r[8];
#pragma unroll
        for (int j = 0; j < 8; j++) {
            float v = 0.5f * (acc[j] + part[j]);
            r[j] = fminf(fmaxf(v, 0.f), 6.f);
        }
        float* o = out + (size_t)i * 64 + lane * 8;
        *(float4*)(o)     = make_float4(r[0], r[1], r[2], r[3]);
        *(float4*)(o + 4) = make_float4(r[4], r[5], r[6], r[7]);
    }
}

// ---------------------------------------------------------------------------
extern "C" void kernel_launch(void* const* d_in, const int* in_sizes, int n_in,
                              void* d_out, int out_size)
{
    const float* input = (const float*)d_in[0];
    const int*   edge  = (const int*)  d_in[1];
    const float* Wh    = (const float*)d_in[2];
    const float* Wl    = (const float*)d_in[3];
    const float* ah    = (const float*)d_in[4];
    const float* al    = (const float*)d_in[5];
    float* out = (float*)d_out;

    const int* dst = edge + E_EDGES;

    cudaFuncSetAttribute(k_gemm_mma, cudaFuncAttributeMaxDynamicSharedMemorySize, SM_TOTAL);

    k_wprep<<<32, 256>>>(Wh, Wl);

    const int gemmBlocks = (N_NODES + 127) / 128;   // 782
    k_gemm_mma<<<gemmBlocks, 256, SM_TOTAL>>>(input, ah, al);

    const int warpBlocks = (N_NODES + 7) / 8;
    k_agg<<<warpBlocks, 256>>>(dst);
    k_out<<<warpBlocks, 256>>>(dst, out);
}